// round 1
// baseline (speedup 1.0000x reference)
#include <cuda_runtime.h>

// GNN first layer, fused per protein:
//   out = relu( residues@Wr  +  atoms@Wv  +  mean_valid(atoms[same])@Wsr  +  mean_valid(atoms[diff])@Wdr )
// Key identity: neighbor aggregation is linear -> gather-sum 12-dim atom rows, project once.
//
// Assumptions (to be validated by this round's bench):
//   * index tensors same*/diff* are int32 (JAX default x64-disabled)
//   * d_out is float32, concatenation [res0 | same0 | diff0 | res1 | same1 | diff1]

namespace {
constexpr int NA  = 100000;   // atoms per protein
constexpr int AD  = 12;       // atom one-hot dim
constexpr int RD  = 1024;     // residue embedding dim
constexpr int FD  = 128;      // filters
constexpr int KN  = 10;       // neighbors
constexpr int MT  = 128;      // M tile (rows per CTA)
constexpr int KB  = 8;        // K chunk
constexpr int NCH = RD / KB;  // 128 chunks
constexpr long long NF = (long long)NA * FD;  // 12,800,000
constexpr long long NK = (long long)NA * KN;  //  1,000,000

struct Smem {
  float As[2][KB][MT];   // A tile, k-major (transposed on store)
  float Bs[2][KB][FD];   // B tile (Wr rows)
  float Wv[AD * FD];
  float Wsr[AD * FD];
  float Wdr[AD * FD];
  float at[MT][AD];      // atoms row of each tile row
  float ss[MT][AD];      // masked-mean gather-sum over 'same' neighbors
  float sd[MT][AD];      // masked-mean gather-sum over 'diff' neighbors
};
}  // namespace

__global__ void idx2f_kernel(const int* __restrict__ src, float* __restrict__ dst, int n) {
  int i = blockIdx.x * blockDim.x + threadIdx.x;
  if (i < n) dst[i] = (float)src[i];
}

__global__ void __launch_bounds__(256, 2)
fused_gnn_kernel(const float* __restrict__ atoms, const float* __restrict__ residues,
                 const int* __restrict__ same, const int* __restrict__ diff,
                 const float* __restrict__ Wv, const float* __restrict__ Wr,
                 const float* __restrict__ Wsr, const float* __restrict__ Wdr,
                 float* __restrict__ outp) {
  extern __shared__ char smem_raw[];
  Smem& sm = *reinterpret_cast<Smem*>(smem_raw);
  const int tid = threadIdx.x;
  const int r0  = blockIdx.x * MT;

  // ---- stage the three small [12,128] weight matrices ----
  for (int i = tid; i < AD * FD; i += 256) {
    sm.Wv[i]  = Wv[i];
    sm.Wsr[i] = Wsr[i];
    sm.Wdr[i] = Wdr[i];
  }

  // ---- prepass: per-row atoms vec + masked-mean neighbor atom sums ----
  // warp-per-row; lanes 0..11 own one atom component each; neighbor indices
  // are loaded by lanes 0..19 and broadcast via shfl so 12 lanes issue 20
  // independent (MLP'd) gather loads that all hit L2 (atoms = 4.8 MB).
  const int warp = tid >> 5, lane = tid & 31;
  for (int rr = 0; rr < MT / 8; rr++) {  // 8 warps x 16 rows
    int i = warp * (MT / 8) + rr;
    int g = r0 + i;
    float av = 0.f;
    int idxreg = -1;
    if (g < NA) {
      if (lane < AD) av = atoms[(long long)g * AD + lane];
      if (lane < KN)          idxreg = same[(long long)g * KN + lane];
      else if (lane < 2 * KN) idxreg = diff[(long long)g * KN + (lane - KN)];
    }
    int sidx[KN], didx[KN];
#pragma unroll
    for (int k = 0; k < KN; k++) {
      sidx[k] = __shfl_sync(0xffffffffu, idxreg, k);
      didx[k] = __shfl_sync(0xffffffffu, idxreg, KN + k);
    }
    float ssum = 0.f, dsum = 0.f;
    int scnt = 0, dcnt = 0;
#pragma unroll
    for (int k = 0; k < KN; k++) {
      if (sidx[k] > -1) { scnt++; if (lane < AD) ssum += atoms[(long long)sidx[k] * AD + lane]; }
      if (didx[k] > -1) { dcnt++; if (lane < AD) dsum += atoms[(long long)didx[k] * AD + lane]; }
    }
    float is  = 1.f / (float)(scnt > 1 ? scnt : 1);
    float idn = 1.f / (float)(dcnt > 1 ? dcnt : 1);
    if (lane < AD) {
      sm.at[i][lane] = av;
      sm.ss[i][lane] = ssum * is;
      sm.sd[i][lane] = dsum * idn;
    }
  }

  // ---- mainloop: C[128,128] = residues_tile[128,1024] @ Wr[1024,128] ----
  const int am = tid >> 1, ak = (tid & 1) * 4;   // A loader: row am, k-offset ak (1 float4/thread)
  const int bk = tid >> 5, bc = (tid & 31) * 4;  // B loader: Wr row bk, col bc  (1 float4/thread)
  const int ty = tid >> 4, tx = tid & 15;
  const int m0 = ty * 8, c0 = tx * 8;            // 8x8 outputs per thread

  float acc[8][8];
#pragma unroll
  for (int i = 0; i < 8; i++)
#pragma unroll
    for (int j = 0; j < 8; j++) acc[i][j] = 0.f;

  float4 ra, rb;
  auto ldAB = [&](int kc) {
    int g = r0 + am;
    ra = (g < NA) ? *(const float4*)(residues + (long long)g * RD + kc * KB + ak)
                  : make_float4(0.f, 0.f, 0.f, 0.f);
    rb = *(const float4*)(Wr + (long long)(kc * KB + bk) * FD + bc);
  };
  auto stAB = [&](int buf) {
    sm.As[buf][ak + 0][am] = ra.x;
    sm.As[buf][ak + 1][am] = ra.y;
    sm.As[buf][ak + 2][am] = ra.z;
    sm.As[buf][ak + 3][am] = ra.w;
    *(float4*)&sm.Bs[buf][bk][bc] = rb;
  };

  ldAB(0);
  stAB(0);
  __syncthreads();

  for (int kc = 0; kc < NCH; kc++) {
    int cur = kc & 1;
    if (kc + 1 < NCH) ldAB(kc + 1);  // prefetch next chunk to registers
#pragma unroll
    for (int k = 0; k < KB; k++) {
      float a[8], b[8];
      *(float4*)(a)     = *(const float4*)&sm.As[cur][k][m0];
      *(float4*)(a + 4) = *(const float4*)&sm.As[cur][k][m0 + 4];
      *(float4*)(b)     = *(const float4*)&sm.Bs[cur][k][c0];
      *(float4*)(b + 4) = *(const float4*)&sm.Bs[cur][k][c0 + 4];
#pragma unroll
      for (int i = 0; i < 8; i++)
#pragma unroll
        for (int j = 0; j < 8; j++) acc[i][j] += a[i] * b[j];
    }
    if (kc + 1 < NCH) {
      stAB(cur ^ 1);       // write other buffer (its readers finished last iter)
      __syncthreads();
    }
  }

  // ---- fused epilogue: + atoms@Wv + meanS@Wsr + meanD@Wdr, relu ----
#pragma unroll
  for (int a = 0; a < AD; a++) {
    float wv[8], wsr[8], wdr[8];
    *(float4*)(wv)      = *(const float4*)&sm.Wv[a * FD + c0];
    *(float4*)(wv + 4)  = *(const float4*)&sm.Wv[a * FD + c0 + 4];
    *(float4*)(wsr)     = *(const float4*)&sm.Wsr[a * FD + c0];
    *(float4*)(wsr + 4) = *(const float4*)&sm.Wsr[a * FD + c0 + 4];
    *(float4*)(wdr)     = *(const float4*)&sm.Wdr[a * FD + c0];
    *(float4*)(wdr + 4) = *(const float4*)&sm.Wdr[a * FD + c0 + 4];
#pragma unroll
    for (int i = 0; i < 8; i++) {
      int ri = m0 + i;
      float u = sm.at[ri][a], v = sm.ss[ri][a], w = sm.sd[ri][a];
#pragma unroll
      for (int j = 0; j < 8; j++)
        acc[i][j] += u * wv[j] + v * wsr[j] + w * wdr[j];
    }
  }

#pragma unroll
  for (int i = 0; i < 8; i++) {
    int g = r0 + m0 + i;
    if (g < NA) {
      float4 o0, o1;
      o0.x = fmaxf(acc[i][0], 0.f); o0.y = fmaxf(acc[i][1], 0.f);
      o0.z = fmaxf(acc[i][2], 0.f); o0.w = fmaxf(acc[i][3], 0.f);
      o1.x = fmaxf(acc[i][4], 0.f); o1.y = fmaxf(acc[i][5], 0.f);
      o1.z = fmaxf(acc[i][6], 0.f); o1.w = fmaxf(acc[i][7], 0.f);
      *(float4*)(outp + (long long)g * FD + c0)     = o0;
      *(float4*)(outp + (long long)g * FD + c0 + 4) = o1;
    }
  }
}

extern "C" void kernel_launch(void* const* d_in, const int* in_sizes, int n_in,
                              void* d_out, int out_size) {
  const float* atoms0 = (const float*)d_in[0];
  const float* resd0  = (const float*)d_in[1];
  const int*   same0  = (const int*)d_in[2];
  const int*   diff0  = (const int*)d_in[3];
  const float* atoms1 = (const float*)d_in[4];
  const float* resd1  = (const float*)d_in[5];
  const int*   same1  = (const int*)d_in[6];
  const int*   diff1  = (const int*)d_in[7];
  const float* Wv  = (const float*)d_in[8];
  const float* Wr  = (const float*)d_in[9];
  const float* Wsr = (const float*)d_in[10];
  const float* Wdr = (const float*)d_in[11];
  float* out = (float*)d_out;

  // 52 KB dynamic smem > 48 KB default static limit
  cudaFuncSetAttribute(fused_gnn_kernel,
                       cudaFuncAttributeMaxDynamicSharedMemorySize, (int)sizeof(Smem));

  // index passthrough regions (cast to float; values < 2^24 so exact)
  const int nk = (int)NK;
  idx2f_kernel<<<(nk + 255) / 256, 256>>>(same0, out + NF, nk);
  idx2f_kernel<<<(nk + 255) / 256, 256>>>(diff0, out + NF + NK, nk);
  idx2f_kernel<<<(nk + 255) / 256, 256>>>(same1, out + 2 * NF + 2 * NK, nk);
  idx2f_kernel<<<(nk + 255) / 256, 256>>>(diff1, out + 2 * NF + 3 * NK, nk);

  dim3 grid((NA + MT - 1) / MT);  // 782
  fused_gnn_kernel<<<grid, 256, sizeof(Smem)>>>(atoms0, resd0, same0, diff0,
                                                Wv, Wr, Wsr, Wdr, out);
  fused_gnn_kernel<<<grid, 256, sizeof(Smem)>>>(atoms1, resd1, same1, diff1,
                                                Wv, Wr, Wsr, Wdr, out + NF + 2 * NK);
}

// round 4
// speedup vs baseline: 1.0936x; 1.0936x over previous
#include <cuda_runtime.h>
#include <cuda_bf16.h>
#include <cstdint>

// out = relu( [residues | atoms | meanS(atoms) | meanD(atoms)] @ [Wr; Wv; Wsr; Wdr] )
// Tensor path via baseline-PTX mma.sync m16n8k16 bf16 (3-way split: hi*hi + hi*lo + lo*hi),
// fp32 accumulation in registers. tcgen05 is NOT available (harness ptxas targets sm_103
// without the 'a' feature set), so warp-level HMMA is the tensor ceiling here.

namespace {
constexpr int NA = 100000, AD = 12, RD = 1024, FD = 128, KN = 10;
constexpr int MT = 128;             // rows per CTA
constexpr int KC = 64;              // K chunk (bf16 -> 128B rows, SW128)
constexpr int NCH = RD / KC;        // 16 residue chunks
constexpr int NCHT = NCH + 1;       // +1 ext chunk (atoms|meanS|meanD, rank 36 padded)
constexpr int CTAS = (NA + MT - 1) / MT;  // 782
constexpr long long NF = (long long)NA * FD;
constexpr long long NK = (long long)NA * KN;
constexpr int TILE_B = MT * KC * 2; // 16384 B per bf16 tile

// smem layout (bytes): A hi/lo double-buffered + ext hi/lo (chunk 16 tiles)
constexpr int SM_AHI  = 0;
constexpr int SM_ALO  = 2 * TILE_B;        // 32768
constexpr int SM_EXTH = 4 * TILE_B;        // 65536
constexpr int SM_EXTL = SM_EXTH + TILE_B;  // 81920
constexpr int SM_TOTAL = SM_EXTL + TILE_B; // 98304

constexpr int NFRAGS = NCHT * 16 * 4 * 32;  // [chunk][nfrag16][k16x4][lane32]
}  // namespace

// B pre-baked in mma-fragment order: uint4 = (b_hi0, b_hi1, b_lo0, b_lo1)
__device__ uint4 g_Bfrag[NFRAGS];   // 544 KB, L2-resident

static __device__ __forceinline__ uint32_t sw128(uint32_t off) { return off ^ ((off >> 3) & 0x70); }
static __device__ __forceinline__ uint32_t smem_u32(const void* p) {
  uint32_t a;
  asm("{ .reg .u64 t; cvta.to.shared.u64 t, %1; cvt.u32.u64 %0, t; }" : "=r"(a) : "l"(p));
  return a;
}
static __device__ __forceinline__ void ldm4(uint32_t r[4], uint32_t addr) {
  asm volatile("ldmatrix.sync.aligned.m8n8.x4.shared.b16 {%0,%1,%2,%3}, [%4];"
               : "=r"(r[0]), "=r"(r[1]), "=r"(r[2]), "=r"(r[3]) : "r"(addr));
}
static __device__ __forceinline__ void mma16816(float c[4], const uint32_t a[4],
                                                uint32_t b0, uint32_t b1) {
  asm volatile(
      "mma.sync.aligned.m16n8k16.row.col.f32.bf16.bf16.f32 "
      "{%0,%1,%2,%3}, {%4,%5,%6,%7}, {%8,%9}, {%0,%1,%2,%3};"
      : "+f"(c[0]), "+f"(c[1]), "+f"(c[2]), "+f"(c[3])
      : "r"(a[0]), "r"(a[1]), "r"(a[2]), "r"(a[3]), "r"(b0), "r"(b1));
}
static __device__ __forceinline__ uint16_t bfbits(__nv_bfloat16 h) {
  return *reinterpret_cast<uint16_t*>(&h);
}

// ---- pre-kernel: weights -> B fragments (hi/lo) in exact mma layout ----
__global__ void wfrag_kernel(const float* __restrict__ Wr, const float* __restrict__ Wv,
                             const float* __restrict__ Wsr, const float* __restrict__ Wdr) {
  int i = blockIdx.x * blockDim.x + threadIdx.x;
  if (i >= NFRAGS) return;
  int lane = i & 31, t = (i >> 5) & 3, fn = (i >> 7) & 15, c = i >> 11;
  int n = fn * 8 + (lane >> 2);
  int k0 = t * 16 + 2 * (lane & 3);
  float v[4];
#pragma unroll
  for (int e = 0; e < 4; e++) {
    int kk = k0 + (e & 1) + (e >> 1) * 8;  // {k0, k0+1, k0+8, k0+9}
    float val = 0.f;
    if (c < NCH)            val = Wr[(c * KC + kk) * FD + n];
    else if (kk < AD)       val = Wv[kk * FD + n];
    else if (kk < 2 * AD)   val = Wsr[(kk - AD) * FD + n];
    else if (kk < 3 * AD)   val = Wdr[(kk - 2 * AD) * FD + n];
    v[e] = val;
  }
  uint16_t h[4], l[4];
#pragma unroll
  for (int e = 0; e < 4; e++) {
    __nv_bfloat16 hb = __float2bfloat16_rn(v[e]);
    __nv_bfloat16 lb = __float2bfloat16_rn(v[e] - __bfloat162float(hb));
    h[e] = bfbits(hb); l[e] = bfbits(lb);
  }
  uint4 out;
  out.x = (uint32_t)h[0] | ((uint32_t)h[1] << 16);  // b_hi0 (k0,k0+1)
  out.y = (uint32_t)h[2] | ((uint32_t)h[3] << 16);  // b_hi1 (k0+8,k0+9)
  out.z = (uint32_t)l[0] | ((uint32_t)l[1] << 16);  // b_lo0
  out.w = (uint32_t)l[2] | ((uint32_t)l[3] << 16);  // b_lo1
  g_Bfrag[i] = out;
}

// ---- index passthrough (int -> float, exact below 2^24) ----
__global__ void idxcast_kernel(const int* __restrict__ s0, const int* __restrict__ d0,
                               const int* __restrict__ s1, const int* __restrict__ d1,
                               float* __restrict__ out) {
  long long i = (long long)blockIdx.x * blockDim.x + threadIdx.x;
  if (i >= 4 * NK) return;
  int reg = (int)(i / NK);
  long long j = i % NK;
  const int* src = reg == 0 ? s0 : reg == 1 ? d0 : reg == 2 ? s1 : d1;
  long long base = reg == 0 ? NF : reg == 1 ? NF + NK : reg == 2 ? 2 * NF + 2 * NK
                                                                 : 2 * NF + 3 * NK;
  out[base + j] = (float)src[j];
}

// ---- main fused kernel ----
__global__ void __launch_bounds__(256)
gnn_mma_kernel(const float* __restrict__ atoms0, const float* __restrict__ resd0,
               const int* __restrict__ same0, const int* __restrict__ diff0,
               const float* __restrict__ atoms1, const float* __restrict__ resd1,
               const int* __restrict__ same1, const int* __restrict__ diff1,
               float* __restrict__ out) {
  extern __shared__ char smem[];
  const int tid = threadIdx.x, wid = tid >> 5, lane = tid & 31;
  const int p = blockIdx.x / CTAS, tile = blockIdx.x % CTAS;
  const float* atoms = p ? atoms1 : atoms0;
  const float* resd  = p ? resd1  : resd0;
  const int*   same  = p ? same1  : same0;
  const int*   diff  = p ? diff1  : diff0;
  float* outp = out + (p ? (NF + 2 * NK) : 0);
  const int r0 = tile * MT;
  const uint32_t sbase = smem_u32(smem);

  // zero ext hi/lo tiles (pad cols + invalid tail rows)
  {
    uint4 z = make_uint4(0, 0, 0, 0);
    uint4* e = (uint4*)(smem + SM_EXTH);
#pragma unroll
    for (int j = 0; j < 8; j++) e[tid + 256 * j] = z;   // 2 tiles x 1024 uint4
  }
  __syncthreads();

  // ---- prepass: ext rows = [atoms | meanSame | meanDiff | 0] as bf16 hi/lo ----
  for (int rr = 0; rr < 16; rr++) {
    int i = wid * 16 + rr;
    long long g = r0 + i;
    float av = 0.f;
    int idxreg = -1;
    if (g < NA) {
      if (lane < AD) av = atoms[g * AD + lane];
      if (lane < KN)          idxreg = same[g * KN + lane];
      else if (lane < 2 * KN) idxreg = diff[g * KN + (lane - KN)];
    }
    int sidx[KN], didx[KN];
#pragma unroll
    for (int k = 0; k < KN; k++) {
      sidx[k] = __shfl_sync(0xffffffffu, idxreg, k);
      didx[k] = __shfl_sync(0xffffffffu, idxreg, KN + k);
    }
    float ssum = 0.f, dsum = 0.f;
    int scnt = 0, dcnt = 0;
#pragma unroll
    for (int k = 0; k < KN; k++) {
      if (sidx[k] > -1) { scnt++; if (lane < AD) ssum += atoms[(long long)sidx[k] * AD + lane]; }
      if (didx[k] > -1) { dcnt++; if (lane < AD) dsum += atoms[(long long)didx[k] * AD + lane]; }
    }
    if (lane < AD && g < NA) {
      float vals[3] = {av, ssum * (1.f / (float)(scnt > 1 ? scnt : 1)),
                           dsum * (1.f / (float)(dcnt > 1 ? dcnt : 1))};
#pragma unroll
      for (int q = 0; q < 3; q++) {
        __nv_bfloat16 hb = __float2bfloat16_rn(vals[q]);
        __nv_bfloat16 lb = __float2bfloat16_rn(vals[q] - __bfloat162float(hb));
        uint32_t off = sw128((uint32_t)i * 128 + (uint32_t)(q * AD + lane) * 2);
        *(__nv_bfloat16*)(smem + SM_EXTH + off) = hb;
        *(__nv_bfloat16*)(smem + SM_EXTL + off) = lb;
      }
    }
  }
  __syncthreads();  // ext tiles final (read at chunk 16)

  // warp tile: 2x4 grid, each warp 64(M) x 32(N)
  const int wm = (wid >> 2) * 64;
  const int fnBase = (wid & 3) * 4;   // absolute n-frag base (n = fnBase*8)
  float acc[4][4][4];
#pragma unroll
  for (int a = 0; a < 4; a++)
#pragma unroll
    for (int b = 0; b < 4; b++)
#pragma unroll
      for (int e = 0; e < 4; e++) acc[a][b][e] = 0.f;

  // A staging: per thread 32 floats per chunk (4 groups of 8)
  float va[32];
  auto ldgA = [&](int c) {
#pragma unroll
    for (int j = 0; j < 4; j++) {
      int u = tid + 256 * j;
      int r = u >> 3, k0 = (u & 7) * 8;
      long long g = r0 + r;
      float4 f0, f1;
      if (g < NA) {
        const float* s = resd + g * RD + c * KC + k0;
        f0 = *(const float4*)s;
        f1 = *(const float4*)(s + 4);
      } else {
        f0 = f1 = make_float4(0.f, 0.f, 0.f, 0.f);
      }
      va[j * 8 + 0] = f0.x; va[j * 8 + 1] = f0.y; va[j * 8 + 2] = f0.z; va[j * 8 + 3] = f0.w;
      va[j * 8 + 4] = f1.x; va[j * 8 + 5] = f1.y; va[j * 8 + 6] = f1.z; va[j * 8 + 7] = f1.w;
    }
  };
  auto stsA = [&](int s) {
    char* H = smem + SM_AHI + s * TILE_B;
    char* L = smem + SM_ALO + s * TILE_B;
#pragma unroll
    for (int j = 0; j < 4; j++) {
      int u = tid + 256 * j;
      int r = u >> 3, k0 = (u & 7) * 8;
      uint16_t hh[8], ll[8];
#pragma unroll
      for (int e = 0; e < 8; e++) {
        float v = va[j * 8 + e];
        __nv_bfloat16 hb = __float2bfloat16_rn(v);
        __nv_bfloat16 lb = __float2bfloat16_rn(v - __bfloat162float(hb));
        hh[e] = bfbits(hb); ll[e] = bfbits(lb);
      }
      uint32_t so = sw128((uint32_t)r * 128 + (uint32_t)k0 * 2);
      *(uint4*)(H + so) = *(const uint4*)hh;
      *(uint4*)(L + so) = *(const uint4*)ll;
    }
  };

  auto computeChunk = [&](uint32_t hiB, uint32_t loB, int c) {
    uint4 bcur[4], bnxt[4];
    const int base = (c * 16 + fnBase) * 4;  // frag row index
#pragma unroll
    for (int nf = 0; nf < 4; nf++) bcur[nf] = g_Bfrag[((base + nf * 4) << 5) + lane];
#pragma unroll
    for (int t = 0; t < 4; t++) {
      if (t < 3) {
#pragma unroll
        for (int nf = 0; nf < 4; nf++)
          bnxt[nf] = g_Bfrag[((base + nf * 4 + (t + 1)) << 5) + lane];
      }
      uint32_t colsw = sw128(((uint32_t)(lane & 15)) * 128 + (uint32_t)(t * 2 + (lane >> 4)) * 16);
      uint32_t ah[4][4], al[4][4];
#pragma unroll
      for (int mf = 0; mf < 4; mf++) {
        uint32_t off = (uint32_t)wm * 128 + (uint32_t)mf * 2048 + colsw;
        ldm4(ah[mf], hiB + off);
        ldm4(al[mf], loB + off);
      }
#pragma unroll
      for (int mf = 0; mf < 4; mf++)
#pragma unroll
        for (int nf = 0; nf < 4; nf++) {
          mma16816(acc[mf][nf], ah[mf], bcur[nf].x, bcur[nf].y);  // hi*hi
          mma16816(acc[mf][nf], ah[mf], bcur[nf].z, bcur[nf].w);  // hi*lo
          mma16816(acc[mf][nf], al[mf], bcur[nf].x, bcur[nf].y);  // lo*hi
        }
      if (t < 3) {
#pragma unroll
        for (int nf = 0; nf < 4; nf++) bcur[nf] = bnxt[nf];
      }
    }
  };

  // ---- mainloop: 16 residue chunks double-buffered, then ext chunk ----
  ldgA(0);
  stsA(0);
  __syncthreads();
  for (int c = 0; c < NCH; c++) {
    if (c + 1 < NCH) ldgA(c + 1);
    computeChunk(sbase + SM_AHI + (c & 1) * TILE_B, sbase + SM_ALO + (c & 1) * TILE_B, c);
    if (c + 1 < NCH) {
      __syncthreads();          // all warps done with buffer (c+1)&1
      stsA((c + 1) & 1);
      __syncthreads();          // staged data visible
    }
  }
  computeChunk(sbase + SM_EXTH, sbase + SM_EXTL, NCH);

  // ---- epilogue: relu + coalesced-sector float2 stores straight from fragments ----
  const int wn = (wid & 3) * 32;
#pragma unroll
  for (int mf = 0; mf < 4; mf++) {
    long long r = (long long)r0 + wm + mf * 16 + (lane >> 2);
#pragma unroll
    for (int nf = 0; nf < 4; nf++) {
      int cb = wn + nf * 8 + 2 * (lane & 3);
      if (r < NA) {
        float2 w;
        w.x = fmaxf(acc[mf][nf][0], 0.f);
        w.y = fmaxf(acc[mf][nf][1], 0.f);
        *(float2*)(outp + r * FD + cb) = w;
      }
      if (r + 8 < NA) {
        float2 w;
        w.x = fmaxf(acc[mf][nf][2], 0.f);
        w.y = fmaxf(acc[mf][nf][3], 0.f);
        *(float2*)(outp + (r + 8) * FD + cb) = w;
      }
    }
  }
}

extern "C" void kernel_launch(void* const* d_in, const int* in_sizes, int n_in,
                              void* d_out, int out_size) {
  const float* atoms0 = (const float*)d_in[0];
  const float* resd0  = (const float*)d_in[1];
  const int*   same0  = (const int*)d_in[2];
  const int*   diff0  = (const int*)d_in[3];
  const float* atoms1 = (const float*)d_in[4];
  const float* resd1  = (const float*)d_in[5];
  const int*   same1  = (const int*)d_in[6];
  const int*   diff1  = (const int*)d_in[7];
  const float* Wv  = (const float*)d_in[8];
  const float* Wr  = (const float*)d_in[9];
  const float* Wsr = (const float*)d_in[10];
  const float* Wdr = (const float*)d_in[11];
  float* out = (float*)d_out;

  cudaFuncSetAttribute(gnn_mma_kernel, cudaFuncAttributeMaxDynamicSharedMemorySize, SM_TOTAL);

  wfrag_kernel<<<(NFRAGS + 255) / 256, 256>>>(Wr, Wv, Wsr, Wdr);
  long long in4 = 4 * NK;
  idxcast_kernel<<<(int)((in4 + 255) / 256), 256>>>(same0, diff0, same1, diff1, out);
  gnn_mma_kernel<<<2 * CTAS, 256, SM_TOTAL>>>(atoms0, resd0, same0, diff0,
                                              atoms1, resd1, same1, diff1, out);
}

// round 7
// speedup vs baseline: 2.3011x; 2.1042x over previous
#include <cuda_runtime.h>
#include <cuda_bf16.h>
#include <cstdint>

// out = relu( [residues | atoms | meanS(atoms) | meanD(atoms)] @ [Wr; Wv; Wsr; Wdr] )
// mma.sync m16n8k16 bf16, 3-way split (hi*hi + hi*lo + lo*hi), fp32 reg accum.
// R6 = R5 with the stage-read swizzle bug fixed: second float4 must use
// sw128(x+16), NOT sw128(x)+16 (the latter walks off the smem allocation at
// row 127 and corrupts data wherever the swizzle mask has bit 4 set).

namespace {
constexpr int NA = 100000, AD = 12, RD = 1024, FD = 128, KN = 10;
constexpr int MT = 128;             // rows per CTA
constexpr int KC = 64;              // K chunk
constexpr int NCH = RD / KC;        // 16 residue chunks
constexpr int NCHT = NCH + 1;       // +1 ext chunk (atoms|meanS|meanD)
constexpr int CTAS = (NA + MT - 1) / MT;  // 782
constexpr long long NF = (long long)NA * FD;
constexpr long long NK = (long long)NA * KN;
constexpr int TILE_B  = MT * KC * 2;  // 16 KB bf16 tile
constexpr int STAGE_B = MT * KC * 4;  // 32 KB f32 stage

constexpr int SM_AHI = 0;
constexpr int SM_ALO = TILE_B;
constexpr int SM_STG = 2 * TILE_B;                 // 2 stage buffers follow
constexpr int SM_TOTAL = 2 * TILE_B + 2 * STAGE_B; // 96 KB

constexpr int NFRAGS = NCHT * 16 * 4 * 32;  // [chunk][nfrag16][t4][lane32]
}  // namespace

__device__ uint4 g_Bfrag[NFRAGS];  // B in mma-frag order: (hi0,hi1,lo0,lo1)

static __device__ __forceinline__ uint32_t sw128(uint32_t off) { return off ^ ((off >> 3) & 0x70); }
static __device__ __forceinline__ uint32_t smem_u32(const void* p) {
  uint32_t a;
  asm("{ .reg .u64 t; cvta.to.shared.u64 t, %1; cvt.u32.u64 %0, t; }" : "=r"(a) : "l"(p));
  return a;
}
static __device__ __forceinline__ void ldm4(uint32_t r[4], uint32_t addr) {
  asm volatile("ldmatrix.sync.aligned.m8n8.x4.shared.b16 {%0,%1,%2,%3}, [%4];"
               : "=r"(r[0]), "=r"(r[1]), "=r"(r[2]), "=r"(r[3]) : "r"(addr));
}
static __device__ __forceinline__ void mma16816(float c[4], const uint32_t a[4],
                                                uint32_t b0, uint32_t b1) {
  asm volatile(
      "mma.sync.aligned.m16n8k16.row.col.f32.bf16.bf16.f32 "
      "{%0,%1,%2,%3}, {%4,%5,%6,%7}, {%8,%9}, {%0,%1,%2,%3};"
      : "+f"(c[0]), "+f"(c[1]), "+f"(c[2]), "+f"(c[3])
      : "r"(a[0]), "r"(a[1]), "r"(a[2]), "r"(a[3]), "r"(b0), "r"(b1));
}
static __device__ __forceinline__ uint16_t bfbits(__nv_bfloat16 h) {
  return *reinterpret_cast<uint16_t*>(&h);
}
static __device__ __forceinline__ void cpasync16(uint32_t dst, const void* src, int srcsz) {
  asm volatile("cp.async.cg.shared.global [%0], [%1], 16, %2;"
               :: "r"(dst), "l"(src), "r"(srcsz) : "memory");
}
#define CP_COMMIT()  asm volatile("cp.async.commit_group;" ::: "memory")
#define CP_WAIT(n)   asm volatile("cp.async.wait_group %0;" :: "n"(n) : "memory")

// ---- prep: B-fragment bake + index passthrough, merged into ONE launch ----
__global__ void prep_kernel(const float* __restrict__ Wr, const float* __restrict__ Wv,
                            const float* __restrict__ Wsr, const float* __restrict__ Wdr,
                            const int* __restrict__ s0, const int* __restrict__ d0,
                            const int* __restrict__ s1, const int* __restrict__ d1,
                            float* __restrict__ out) {
  long long i = (long long)blockIdx.x * blockDim.x + threadIdx.x;
  if (i < NFRAGS) {
    int ii = (int)i;
    int lane = ii & 31, t = (ii >> 5) & 3, fn = (ii >> 7) & 15, c = ii >> 11;
    int n = fn * 8 + (lane >> 2);
    int k0 = t * 16 + 2 * (lane & 3);
    uint16_t h[4], l[4];
#pragma unroll
    for (int e = 0; e < 4; e++) {
      int kk = k0 + (e & 1) + (e >> 1) * 8;  // {k0,k0+1,k0+8,k0+9}
      float val = 0.f;
      if (c < NCH)          val = Wr[(c * KC + kk) * FD + n];
      else if (kk < AD)     val = Wv[kk * FD + n];
      else if (kk < 2 * AD) val = Wsr[(kk - AD) * FD + n];
      else if (kk < 3 * AD) val = Wdr[(kk - 2 * AD) * FD + n];
      __nv_bfloat16 hb = __float2bfloat16_rn(val);
      __nv_bfloat16 lb = __float2bfloat16_rn(val - __bfloat162float(hb));
      h[e] = bfbits(hb); l[e] = bfbits(lb);
    }
    uint4 o;
    o.x = (uint32_t)h[0] | ((uint32_t)h[1] << 16);
    o.y = (uint32_t)h[2] | ((uint32_t)h[3] << 16);
    o.z = (uint32_t)l[0] | ((uint32_t)l[1] << 16);
    o.w = (uint32_t)l[2] | ((uint32_t)l[3] << 16);
    g_Bfrag[ii] = o;
  }
  if (i < 4 * NK) {
    int reg = (int)(i / NK);
    long long j = i % NK;
    const int* src = reg == 0 ? s0 : reg == 1 ? d0 : reg == 2 ? s1 : d1;
    long long base = reg == 0 ? NF : reg == 1 ? NF + NK
                   : reg == 2 ? 2 * NF + 2 * NK : 2 * NF + 3 * NK;
    out[base + j] = (float)src[j];
  }
}

// ---- main fused kernel ----
__global__ void __launch_bounds__(256, 2)
gnn_mma_kernel(const float* __restrict__ atoms0, const float* __restrict__ resd0,
               const int* __restrict__ same0, const int* __restrict__ diff0,
               const float* __restrict__ atoms1, const float* __restrict__ resd1,
               const int* __restrict__ same1, const int* __restrict__ diff1,
               float* __restrict__ out) {
  extern __shared__ char smem[];
  const int tid = threadIdx.x, wid = tid >> 5, lane = tid & 31;
  const int p = blockIdx.x / CTAS, tile = blockIdx.x % CTAS;
  const float* atoms = p ? atoms1 : atoms0;
  const float* resd  = p ? resd1  : resd0;
  const int*   same  = p ? same1  : same0;
  const int*   diff  = p ? diff1  : diff0;
  float* outp = out + (p ? (NF + 2 * NK) : 0);
  const int r0 = tile * MT;
  const uint32_t sbase = smem_u32(smem);
  const uint32_t hiB = sbase + SM_AHI, loB = sbase + SM_ALO;

  // cp.async prefetch of residue chunk c into stage buffer buf
  auto stageChunk = [&](int c, int buf) {
    uint32_t sb = sbase + SM_STG + buf * STAGE_B;
#pragma unroll
    for (int j = 0; j < 8; j++) {
      int u = tid + 256 * j;            // 16B unit: r = u>>4, kq = u&15
      int r = u >> 4, kq = u & 15;
      long long g = r0 + r;
      const float* src = resd + (g < NA ? g * RD + (long long)c * KC + kq * 4 : 0);
      cpasync16(sb + sw128((uint32_t)r * 256 + (uint32_t)kq * 16), src, g < NA ? 16 : 0);
    }
    CP_COMMIT();
  };
  stageChunk(0, 0);

  // zero A hi/lo tiles (ext chunk pad + tail rows)
  {
    uint4 z = make_uint4(0, 0, 0, 0);
    uint4* e = (uint4*)(smem + SM_AHI);
#pragma unroll
    for (int j = 0; j < 8; j++) e[tid + 256 * j] = z;  // 32 KB
  }
  __syncthreads();

  // ---- prepass: ext rows = [atoms | meanSame | meanDiff | 0] into A tiles ----
  for (int rr = 0; rr < 16; rr++) {
    int i = wid * 16 + rr;
    long long g = r0 + i;
    float av = 0.f;
    int idxreg = -1;
    if (g < NA) {
      if (lane < AD) av = atoms[g * AD + lane];
      if (lane < KN)          idxreg = same[g * KN + lane];
      else if (lane < 2 * KN) idxreg = diff[g * KN + (lane - KN)];
    }
    float ssum = 0.f, dsum = 0.f;
    int scnt = 0, dcnt = 0;
#pragma unroll
    for (int k = 0; k < KN; k++) {
      int si = __shfl_sync(0xffffffffu, idxreg, k);
      int di = __shfl_sync(0xffffffffu, idxreg, KN + k);
      if (si > -1) { scnt++; if (lane < AD) ssum += atoms[(long long)si * AD + lane]; }
      if (di > -1) { dcnt++; if (lane < AD) dsum += atoms[(long long)di * AD + lane]; }
    }
    if (lane < AD && g < NA) {
      float vals[3] = {av, ssum * (1.f / (float)(scnt > 1 ? scnt : 1)),
                           dsum * (1.f / (float)(dcnt > 1 ? dcnt : 1))};
#pragma unroll
      for (int q = 0; q < 3; q++) {
        __nv_bfloat16 hb = __float2bfloat16_rn(vals[q]);
        __nv_bfloat16 lb = __float2bfloat16_rn(vals[q] - __bfloat162float(hb));
        uint32_t off = sw128((uint32_t)i * 128 + (uint32_t)(q * AD + lane) * 2);
        *(__nv_bfloat16*)(smem + SM_AHI + off) = hb;
        *(__nv_bfloat16*)(smem + SM_ALO + off) = lb;
      }
    }
  }
  __syncthreads();

  // warp tile: 2x4 grid, each warp 64(M) x 32(N)
  const int wm = (wid >> 2) * 64;
  const int fnBase = (wid & 3) * 4;
  float acc[4][4][4];
#pragma unroll
  for (int a = 0; a < 4; a++)
#pragma unroll
    for (int b = 0; b < 4; b++)
#pragma unroll
      for (int e = 0; e < 4; e++) acc[a][b][e] = 0.f;

  auto computeChunk = [&](int cb) {  // cb = B-fragment chunk index
#pragma unroll
    for (int t = 0; t < 4; t++) {
      uint4 bcur[4];
#pragma unroll
      for (int nf = 0; nf < 4; nf++)
        bcur[nf] = g_Bfrag[(((cb * 16 + fnBase + nf) * 4 + t) << 5) + lane];
      uint32_t colsw = sw128(((uint32_t)(lane & 15)) * 128 +
                             (uint32_t)(t * 2 + (lane >> 4)) * 16);
#pragma unroll
      for (int mf = 0; mf < 4; mf++) {
        uint32_t off = (uint32_t)wm * 128 + (uint32_t)mf * 2048 + colsw;
        uint32_t ah[4], al[4];
        ldm4(ah, hiB + off);
        ldm4(al, loB + off);
#pragma unroll
        for (int nf = 0; nf < 4; nf++) {
          mma16816(acc[mf][nf], ah, bcur[nf].x, bcur[nf].y);  // hi*hi
          mma16816(acc[mf][nf], ah, bcur[nf].z, bcur[nf].w);  // hi*lo
          mma16816(acc[mf][nf], al, bcur[nf].x, bcur[nf].y);  // lo*hi
        }
      }
    }
  };

  // ---- ext chunk first (B chunk index NCH), from prepass-filled A tiles ----
  computeChunk(NCH);

  // ---- residue chunks 0..15: cp.async double-buffered stage -> convert -> mma ----
  for (int c = 0; c < NCH; c++) {
    if (c + 1 < NCH) { stageChunk(c + 1, (c + 1) & 1); CP_WAIT(1); }
    else             { CP_WAIT(0); }
    __syncthreads();   // stage c ready everywhere; all warps done reading A tiles
    // convert stage -> bf16 hi/lo A tiles
    {
      uint32_t sb = sbase + SM_STG + (c & 1) * STAGE_B;
#pragma unroll
      for (int j = 0; j < 4; j++) {
        int u = tid + 256 * j;
        int r = u >> 3, k0 = (u & 7) * 8;
        uint32_t x = (uint32_t)r * 256 + (uint32_t)k0 * 4;
        uint32_t so0 = sw128(x);        // first 16B unit
        uint32_t so1 = sw128(x + 16);   // second 16B unit — INDEPENDENT swizzle (bugfix)
        float4 f0, f1;
        asm volatile("ld.shared.v4.f32 {%0,%1,%2,%3}, [%4];"
                     : "=f"(f0.x), "=f"(f0.y), "=f"(f0.z), "=f"(f0.w) : "r"(sb + so0));
        asm volatile("ld.shared.v4.f32 {%0,%1,%2,%3}, [%4];"
                     : "=f"(f1.x), "=f"(f1.y), "=f"(f1.z), "=f"(f1.w) : "r"(sb + so1));
        float v[8] = {f0.x, f0.y, f0.z, f0.w, f1.x, f1.y, f1.z, f1.w};
        uint16_t hh[8], ll[8];
#pragma unroll
        for (int e = 0; e < 8; e++) {
          __nv_bfloat16 hb = __float2bfloat16_rn(v[e]);
          __nv_bfloat16 lb = __float2bfloat16_rn(v[e] - __bfloat162float(hb));
          hh[e] = bfbits(hb); ll[e] = bfbits(lb);
        }
        uint32_t ao = sw128((uint32_t)r * 128 + (uint32_t)k0 * 2);
        *(uint4*)(smem + SM_AHI + ao) = *(const uint4*)hh;
        *(uint4*)(smem + SM_ALO + ao) = *(const uint4*)ll;
      }
    }
    __syncthreads();   // converted tiles visible
    computeChunk(c);
  }

  // ---- epilogue: relu + float2 stores straight from fragments ----
  const int wn = (wid & 3) * 32;
#pragma unroll
  for (int mf = 0; mf < 4; mf++) {
    long long r = (long long)r0 + wm + mf * 16 + (lane >> 2);
#pragma unroll
    for (int nf = 0; nf < 4; nf++) {
      int cb = wn + nf * 8 + 2 * (lane & 3);
      if (r < NA) {
        float2 w;
        w.x = fmaxf(acc[mf][nf][0], 0.f);
        w.y = fmaxf(acc[mf][nf][1], 0.f);
        *(float2*)(outp + r * FD + cb) = w;
      }
      if (r + 8 < NA) {
        float2 w;
        w.x = fmaxf(acc[mf][nf][2], 0.f);
        w.y = fmaxf(acc[mf][nf][3], 0.f);
        *(float2*)(outp + (r + 8) * FD + cb) = w;
      }
    }
  }
}

extern "C" void kernel_launch(void* const* d_in, const int* in_sizes, int n_in,
                              void* d_out, int out_size) {
  const float* atoms0 = (const float*)d_in[0];
  const float* resd0  = (const float*)d_in[1];
  const int*   same0  = (const int*)d_in[2];
  const int*   diff0  = (const int*)d_in[3];
  const float* atoms1 = (const float*)d_in[4];
  const float* resd1  = (const float*)d_in[5];
  const int*   same1  = (const int*)d_in[6];
  const int*   diff1  = (const int*)d_in[7];
  const float* Wv  = (const float*)d_in[8];
  const float* Wr  = (const float*)d_in[9];
  const float* Wsr = (const float*)d_in[10];
  const float* Wdr = (const float*)d_in[11];
  float* out = (float*)d_out;

  cudaFuncSetAttribute(gnn_mma_kernel, cudaFuncAttributeMaxDynamicSharedMemorySize, SM_TOTAL);

  long long pn = 4 * NK;  // covers NFRAGS too
  prep_kernel<<<(int)((pn + 255) / 256), 256>>>(Wr, Wv, Wsr, Wdr,
                                                same0, diff0, same1, diff1, out);
  gnn_mma_kernel<<<2 * CTAS, 256, SM_TOTAL>>>(atoms0, resd0, same0, diff0,
                                              atoms1, resd1, same1, diff1, out);
}

// round 9
// speedup vs baseline: 2.6759x; 1.1629x over previous
#include <cuda_runtime.h>
#include <cuda_bf16.h>
#include <cstdint>

// out = relu( [residues | atoms | meanS(atoms) | meanD(atoms)] @ [Wr; Wv; Wsr; Wdr] )
// mma.sync m16n8k16 bf16, 3-way split (hi*hi + hi*lo + lo*hi), fp32 reg accum.
// R9 = R8 with the cp.async visibility race fixed: wait_group is PER-THREAD, so
// every CP_WAIT is now followed by __syncthreads() before reading smem bytes
// written by other threads' async copies (R8 had the barrier before the wait).

namespace {
constexpr int NA = 100000, AD = 12, RD = 1024, FD = 128, KN = 10;
constexpr int MT = 128;             // rows per CTA
constexpr int KC = 64;              // K chunk
constexpr int NCH = RD / KC;        // 16 residue chunks
constexpr int NCHT = NCH + 1;       // +1 ext chunk (atoms|meanS|meanD)
constexpr int CTAS = (NA + MT - 1) / MT;  // 782
constexpr long long NF = (long long)NA * FD;
constexpr long long NK = (long long)NA * KN;

// smem layout (bytes)
constexpr int SM_AHI = 0;                  // 16 KB A hi tile (bf16, 128B rows, sw128)
constexpr int SM_ALO = 16384;              // 16 KB A lo tile
constexpr int SM_STG = 32768;              // 32 KB f32 stage (two 16KB halves, 128B rows)
constexpr int SM_B   = 65536;              // 32 KB B fragments (2048 x uint4, linear)
constexpr int SM_TOTAL = 98304;            // 96 KB -> 2 CTAs/SM

constexpr int NFRAGS = NCHT * 16 * 4 * 32; // [chunk][nfrag16][t4][lane32]
}  // namespace

__device__ uint4 g_Bfrag[NFRAGS];  // B in mma-frag order: (hi0,hi1,lo0,lo1)

static __device__ __forceinline__ uint32_t sw128(uint32_t off) { return off ^ ((off >> 3) & 0x70); }
static __device__ __forceinline__ uint32_t smem_u32(const void* p) {
  uint32_t a;
  asm("{ .reg .u64 t; cvta.to.shared.u64 t, %1; cvt.u32.u64 %0, t; }" : "=r"(a) : "l"(p));
  return a;
}
static __device__ __forceinline__ void ldm4(uint32_t r[4], uint32_t addr) {
  asm volatile("ldmatrix.sync.aligned.m8n8.x4.shared.b16 {%0,%1,%2,%3}, [%4];"
               : "=r"(r[0]), "=r"(r[1]), "=r"(r[2]), "=r"(r[3]) : "r"(addr));
}
static __device__ __forceinline__ void mma16816(float c[4], const uint32_t a[4],
                                                uint32_t b0, uint32_t b1) {
  asm volatile(
      "mma.sync.aligned.m16n8k16.row.col.f32.bf16.bf16.f32 "
      "{%0,%1,%2,%3}, {%4,%5,%6,%7}, {%8,%9}, {%0,%1,%2,%3};"
      : "+f"(c[0]), "+f"(c[1]), "+f"(c[2]), "+f"(c[3])
      : "r"(a[0]), "r"(a[1]), "r"(a[2]), "r"(a[3]), "r"(b0), "r"(b1));
}
static __device__ __forceinline__ uint16_t bfbits(__nv_bfloat16 h) {
  return *reinterpret_cast<uint16_t*>(&h);
}
static __device__ __forceinline__ void cpasync16(uint32_t dst, const void* src, int srcsz) {
  asm volatile("cp.async.cg.shared.global [%0], [%1], 16, %2;"
               :: "r"(dst), "l"(src), "r"(srcsz) : "memory");
}
// pair = {lo: a, hi: b} as bf16x2
static __device__ __forceinline__ uint32_t bf16x2_rn(float a, float b) {
  uint32_t r;
  asm("cvt.rn.bf16x2.f32 %0, %1, %2;" : "=r"(r) : "f"(b), "f"(a));
  return r;
}
#define CP_COMMIT()  asm volatile("cp.async.commit_group;" ::: "memory")
#define CP_WAIT(n)   asm volatile("cp.async.wait_group %0;" :: "n"(n) : "memory")

// ---- prep: B-fragment bake + index passthrough, merged into ONE launch ----
__global__ void prep_kernel(const float* __restrict__ Wr, const float* __restrict__ Wv,
                            const float* __restrict__ Wsr, const float* __restrict__ Wdr,
                            const int* __restrict__ s0, const int* __restrict__ d0,
                            const int* __restrict__ s1, const int* __restrict__ d1,
                            float* __restrict__ out) {
  long long i = (long long)blockIdx.x * blockDim.x + threadIdx.x;
  if (i < NFRAGS) {
    int ii = (int)i;
    int lane = ii & 31, t = (ii >> 5) & 3, fn = (ii >> 7) & 15, c = ii >> 11;
    int n = fn * 8 + (lane >> 2);
    int k0 = t * 16 + 2 * (lane & 3);
    uint16_t h[4], l[4];
#pragma unroll
    for (int e = 0; e < 4; e++) {
      int kk = k0 + (e & 1) + (e >> 1) * 8;  // {k0,k0+1,k0+8,k0+9}
      float val = 0.f;
      if (c < NCH)          val = Wr[(c * KC + kk) * FD + n];
      else if (kk < AD)     val = Wv[kk * FD + n];
      else if (kk < 2 * AD) val = Wsr[(kk - AD) * FD + n];
      else if (kk < 3 * AD) val = Wdr[(kk - 2 * AD) * FD + n];
      __nv_bfloat16 hb = __float2bfloat16_rn(val);
      __nv_bfloat16 lb = __float2bfloat16_rn(val - __bfloat162float(hb));
      h[e] = bfbits(hb); l[e] = bfbits(lb);
    }
    uint4 o;
    o.x = (uint32_t)h[0] | ((uint32_t)h[1] << 16);
    o.y = (uint32_t)h[2] | ((uint32_t)h[3] << 16);
    o.z = (uint32_t)l[0] | ((uint32_t)l[1] << 16);
    o.w = (uint32_t)l[2] | ((uint32_t)l[3] << 16);
    g_Bfrag[ii] = o;
  }
  if (i < 4 * NK) {
    int reg = (int)(i / NK);
    long long j = i % NK;
    const int* src = reg == 0 ? s0 : reg == 1 ? d0 : reg == 2 ? s1 : d1;
    long long base = reg == 0 ? NF : reg == 1 ? NF + NK
                   : reg == 2 ? 2 * NF + 2 * NK : 2 * NF + 3 * NK;
    out[base + j] = (float)src[j];
  }
}

// ---- main fused kernel ----
__global__ void __launch_bounds__(256, 2)
gnn_mma_kernel(const float* __restrict__ atoms0, const float* __restrict__ resd0,
               const int* __restrict__ same0, const int* __restrict__ diff0,
               const float* __restrict__ atoms1, const float* __restrict__ resd1,
               const int* __restrict__ same1, const int* __restrict__ diff1,
               float* __restrict__ out) {
  extern __shared__ char smem[];
  const int tid = threadIdx.x, wid = tid >> 5, lane = tid & 31;
  const int p = blockIdx.x / CTAS, tile = blockIdx.x % CTAS;
  const float* atoms = p ? atoms1 : atoms0;
  const float* resd  = p ? resd1  : resd0;
  const int*   same  = p ? same1  : same0;
  const int*   diff  = p ? diff1  : diff0;
  float* outp = out + (p ? (NF + 2 * NK) : 0);
  const int r0 = tile * MT;
  const uint32_t sbase = smem_u32(smem);
  const uint32_t hiB = sbase + SM_AHI, loB = sbase + SM_ALO;
  const uint32_t stgB = sbase + SM_STG, bB = sbase + SM_B;

  // f32 residues chunk c -> stage (two 16KB halves, 128B rows, sw128)
  auto stageChunk = [&](int c) {
#pragma unroll
    for (int j = 0; j < 8; j++) {
      int u = tid + 256 * j;            // 16B unit: r = u>>4, kq = u&15
      int r = u >> 4, kq = u & 15;
      long long g = r0 + r;
      const float* src = resd + (g < NA ? g * RD + (long long)c * KC + kq * 4 : 0);
      uint32_t dst = stgB + (uint32_t)(kq >> 3) * 16384 +
                     sw128((uint32_t)r * 128 + (uint32_t)(kq & 7) * 16);
      cpasync16(dst, src, g < NA ? 16 : 0);
    }
  };
  // B fragments chunk cb -> smem (straight 32 KB copy, linear)
  auto bstage = [&](int cb) {
    const uint4* src = g_Bfrag + cb * 2048;
#pragma unroll
    for (int j = 0; j < 8; j++) {
      int u = tid + 256 * j;
      cpasync16(bB + (uint32_t)u * 16, src + u, 16);
    }
  };

  // prologue: B(ext) first in FIFO, then stage(0)
  bstage(NCH);   CP_COMMIT();   // G: B(ext)
  stageChunk(0); CP_COMMIT();   // G: stage(0)

  // zero A hi/lo tiles (ext pad cols + tail rows)
  {
    uint4 z = make_uint4(0, 0, 0, 0);
    uint4* e = (uint4*)(smem + SM_AHI);
#pragma unroll
    for (int j = 0; j < 8; j++) e[tid + 256 * j] = z;  // 32 KB
  }
  __syncthreads();

  // ---- prepass: ext rows = [atoms | meanSame | meanDiff | 0] into A tiles ----
  for (int rr = 0; rr < 16; rr++) {
    int i = wid * 16 + rr;
    long long g = r0 + i;
    float av = 0.f;
    int idxreg = -1;
    if (g < NA) {
      if (lane < AD) av = atoms[g * AD + lane];
      if (lane < KN)          idxreg = same[g * KN + lane];
      else if (lane < 2 * KN) idxreg = diff[g * KN + (lane - KN)];
    }
    float ssum = 0.f, dsum = 0.f;
    int scnt = 0, dcnt = 0;
#pragma unroll
    for (int k = 0; k < KN; k++) {
      int si = __shfl_sync(0xffffffffu, idxreg, k);
      int di = __shfl_sync(0xffffffffu, idxreg, KN + k);
      if (si > -1) { scnt++; if (lane < AD) ssum += atoms[(long long)si * AD + lane]; }
      if (di > -1) { dcnt++; if (lane < AD) dsum += atoms[(long long)di * AD + lane]; }
    }
    if (lane < AD && g < NA) {
      float vals[3] = {av, ssum * (1.f / (float)(scnt > 1 ? scnt : 1)),
                           dsum * (1.f / (float)(dcnt > 1 ? dcnt : 1))};
#pragma unroll
      for (int q = 0; q < 3; q++) {
        __nv_bfloat16 hb = __float2bfloat16_rn(vals[q]);
        __nv_bfloat16 lb = __float2bfloat16_rn(vals[q] - __bfloat162float(hb));
        uint32_t off = sw128((uint32_t)i * 128 + (uint32_t)(q * AD + lane) * 2);
        *(__nv_bfloat16*)(smem + SM_AHI + off) = hb;
        *(__nv_bfloat16*)(smem + SM_ALO + off) = lb;
      }
    }
  }

  // warp tile: 2x4 grid, each warp 64(M) x 32(N)
  const int wm = (wid >> 2) * 64;
  const int fnBase = (wid & 3) * 4;
  float acc[4][4][4];
#pragma unroll
  for (int a = 0; a < 4; a++)
#pragma unroll
    for (int b = 0; b < 4; b++)
#pragma unroll
      for (int e = 0; e < 4; e++) acc[a][b][e] = 0.f;

  // compute one chunk: B fragments from smem (conflict-free LDS.128)
  auto computeChunk = [&]() {
#pragma unroll
    for (int t = 0; t < 4; t++) {
      uint4 bq[4];
#pragma unroll
      for (int nf = 0; nf < 4; nf++) {
        uint32_t ba = bB + (uint32_t)((((fnBase + nf) * 4 + t) << 5) + lane) * 16;
        asm volatile("ld.shared.v4.u32 {%0,%1,%2,%3}, [%4];"
                     : "=r"(bq[nf].x), "=r"(bq[nf].y), "=r"(bq[nf].z), "=r"(bq[nf].w)
                     : "r"(ba));
      }
      uint32_t colsw = sw128(((uint32_t)(lane & 15)) * 128 +
                             (uint32_t)(t * 2 + (lane >> 4)) * 16);
#pragma unroll
      for (int mf = 0; mf < 4; mf++) {
        uint32_t off = (uint32_t)wm * 128 + (uint32_t)mf * 2048 + colsw;
        uint32_t ah[4], al[4];
        ldm4(ah, hiB + off);
        ldm4(al, loB + off);
#pragma unroll
        for (int nf = 0; nf < 4; nf++) {
          mma16816(acc[mf][nf], ah, bq[nf].x, bq[nf].y);  // hi*hi
          mma16816(acc[mf][nf], ah, bq[nf].z, bq[nf].w);  // hi*lo
          mma16816(acc[mf][nf], al, bq[nf].x, bq[nf].y);  // lo*hi
        }
      }
    }
  };

  // ---- ext chunk first: wait B(ext), BARRIER, then compute ----
  CP_WAIT(1);       // own B(ext) copies done [stage(0) pending]
  __syncthreads();  // ALL threads' B(ext) copies done (prepass also barriered here)
  computeChunk();

  // ---- residue chunks: single-buffered stage/B/A-tile ----
  for (int c = 0; c < NCH; c++) {
    __syncthreads();            // all warps done with previous compute (B, A free)
    bstage(c); CP_COMMIT();     // G: B(c)
    CP_WAIT(1);                 // own stage(c) copies done [B(c) pending]
    __syncthreads();            // ALL threads' stage(c) copies visible
    // convert stage -> bf16 hi/lo A tiles
#pragma unroll
    for (int j = 0; j < 4; j++) {
      int u = tid + 256 * j;
      int r = u >> 3, k0 = (u & 7) * 8;
      uint32_t half = (uint32_t)(k0 >> 5) * 16384;
      uint32_t x = (uint32_t)r * 128 + (uint32_t)(k0 & 31) * 4;
      float4 f0, f1;
      asm volatile("ld.shared.v4.f32 {%0,%1,%2,%3}, [%4];"
                   : "=f"(f0.x), "=f"(f0.y), "=f"(f0.z), "=f"(f0.w)
                   : "r"(stgB + half + sw128(x)));
      asm volatile("ld.shared.v4.f32 {%0,%1,%2,%3}, [%4];"
                   : "=f"(f1.x), "=f"(f1.y), "=f"(f1.z), "=f"(f1.w)
                   : "r"(stgB + half + sw128(x + 16)));
      float v[8] = {f0.x, f0.y, f0.z, f0.w, f1.x, f1.y, f1.z, f1.w};
      uint32_t hp[4], lp[4];
#pragma unroll
      for (int q = 0; q < 4; q++) {
        uint32_t hpair = bf16x2_rn(v[2 * q], v[2 * q + 1]);
        float h0 = __uint_as_float(hpair << 16);
        float h1 = __uint_as_float(hpair & 0xFFFF0000u);
        hp[q] = hpair;
        lp[q] = bf16x2_rn(v[2 * q] - h0, v[2 * q + 1] - h1);
      }
      uint32_t ao = sw128((uint32_t)r * 128 + (uint32_t)k0 * 2);
      *(uint4*)(smem + SM_AHI + ao) = *(const uint4*)hp;
      *(uint4*)(smem + SM_ALO + ao) = *(const uint4*)lp;
    }
    __syncthreads();            // A tiles ready; stage buffer free
    if (c + 1 < NCH) stageChunk(c + 1);
    CP_COMMIT();                // G: stage(c+1) (empty group at tail keeps FIFO uniform)
    CP_WAIT(1);                 // own B(c) copies done [stage(c+1) pending]
    __syncthreads();            // ALL threads' B(c) copies visible
    computeChunk();
  }

  // ---- epilogue: relu + float2 stores straight from fragments ----
  const int wn = (wid & 3) * 32;
#pragma unroll
  for (int mf = 0; mf < 4; mf++) {
    long long r = (long long)r0 + wm + mf * 16 + (lane >> 2);
#pragma unroll
    for (int nf = 0; nf < 4; nf++) {
      int cb = wn + nf * 8 + 2 * (lane & 3);
      if (r < NA) {
        float2 w;
        w.x = fmaxf(acc[mf][nf][0], 0.f);
        w.y = fmaxf(acc[mf][nf][1], 0.f);
        *(float2*)(outp + r * FD + cb) = w;
      }
      if (r + 8 < NA) {
        float2 w;
        w.x = fmaxf(acc[mf][nf][2], 0.f);
        w.y = fmaxf(acc[mf][nf][3], 0.f);
        *(float2*)(outp + (r + 8) * FD + cb) = w;
      }
    }
  }
}

extern "C" void kernel_launch(void* const* d_in, const int* in_sizes, int n_in,
                              void* d_out, int out_size) {
  const float* atoms0 = (const float*)d_in[0];
  const float* resd0  = (const float*)d_in[1];
  const int*   same0  = (const int*)d_in[2];
  const int*   diff0  = (const int*)d_in[3];
  const float* atoms1 = (const float*)d_in[4];
  const float* resd1  = (const float*)d_in[5];
  const int*   same1  = (const int*)d_in[6];
  const int*   diff1  = (const int*)d_in[7];
  const float* Wv  = (const float*)d_in[8];
  const float* Wr  = (const float*)d_in[9];
  const float* Wsr = (const float*)d_in[10];
  const float* Wdr = (const float*)d_in[11];
  float* out = (float*)d_out;

  cudaFuncSetAttribute(gnn_mma_kernel, cudaFuncAttributeMaxDynamicSharedMemorySize, SM_TOTAL);

  long long pn = 4 * NK;  // covers NFRAGS too
  prep_kernel<<<(int)((pn + 255) / 256), 256>>>(Wr, Wv, Wsr, Wdr,
                                                same0, diff0, same1, diff1, out);
  gnn_mma_kernel<<<2 * CTAS, 256, SM_TOTAL>>>(atoms0, resd0, same0, diff0,
                                              atoms1, resd1, same1, diff1, out);
}